// round 6
// baseline (speedup 1.0000x reference)
#include <cuda_runtime.h>
#include <cuda_fp16.h>
#include <cstdint>
#include <cstddef>

// ---------------------------------------------------------------------------
// Problem constants
// ---------------------------------------------------------------------------
#define M_ROWS 512
#define N_OUT  8192
#define K_IN   8192

#define TILE_M 128
#define TILE_N 128
#define TILE_K 64                 // K elements per chunk
#define KSPLIT 4
#define K_UNIT (K_IN / KSPLIT)    // 2048
#define NCH    (K_UNIT / TILE_K)  // 32 chunks per unit

#define A_STAGE_BYTES (TILE_M * TILE_K * 2)   // 16384 fp16 swizzled
#define B_STAGE_BYTES (TILE_N * TILE_K * 2)   // 16384 fp16 swizzled
#define STAGE_BYTES (A_STAGE_BYTES + B_STAGE_BYTES)
#define STAGES 3
#define SMEM_TOTAL (STAGES * STAGE_BYTES)     // 98304

#define NTHREADS 384              // 8 compute warps + 4 producer warps

// ---------------------------------------------------------------------------
// Scratch (device globals: allocation-free rule)
// ---------------------------------------------------------------------------
__device__ __half g_xh[(size_t)M_ROWS * K_IN];                 // 8 MB fp16 x
__device__ __half g_part[(size_t)KSPLIT * M_ROWS * N_OUT];     // 33.5 MB partials

// ---------------------------------------------------------------------------
// Helpers
// ---------------------------------------------------------------------------
__device__ __forceinline__ uint32_t smem_u32(const void* p) {
    uint32_t a;
    asm("{ .reg .u64 t; cvta.to.shared.u64 t, %1; cvt.u32.u64 %0, t; }"
        : "=r"(a) : "l"(p));
    return a;
}

__device__ __forceinline__ uint32_t sw128(uint32_t off) {
    return off ^ ((off >> 3) & 0x70);
}

__device__ __forceinline__ void cp_async16(uint32_t dst, const void* src) {
    asm volatile("cp.async.cg.shared.global [%0], [%1], 16;\n"
                 :: "r"(dst), "l"(src) : "memory");
}
#define CP_COMMIT() asm volatile("cp.async.commit_group;\n" ::: "memory")
#define CP_WAIT1()  asm volatile("cp.async.wait_group 1;\n" ::: "memory")

__device__ __forceinline__ void ldmatrix_x4(uint32_t* r, uint32_t addr) {
    asm volatile("ldmatrix.sync.aligned.m8n8.x4.shared.b16 {%0,%1,%2,%3}, [%4];\n"
                 : "=r"(r[0]), "=r"(r[1]), "=r"(r[2]), "=r"(r[3]) : "r"(addr));
}

__device__ __forceinline__ void sts64(uint32_t addr, uint32_t a, uint32_t b) {
    asm volatile("st.shared.v2.b32 [%0], {%1,%2};\n"
                 :: "r"(addr), "r"(a), "r"(b) : "memory");
}

__device__ __forceinline__ void mma16816(float* c, const uint32_t* a,
                                         const uint32_t* b) {
    asm volatile(
        "mma.sync.aligned.m16n8k16.row.col.f32.f16.f16.f32 "
        "{%0,%1,%2,%3}, {%4,%5,%6,%7}, {%8,%9}, {%0,%1,%2,%3};\n"
        : "+f"(c[0]), "+f"(c[1]), "+f"(c[2]), "+f"(c[3])
        : "r"(a[0]), "r"(a[1]), "r"(a[2]), "r"(a[3]), "r"(b[0]), "r"(b[1]));
}

// ---------------------------------------------------------------------------
// Kernel 1: x fp32 -> fp16
// ---------------------------------------------------------------------------
__global__ void __launch_bounds__(256) cvt_x_kernel(const float* __restrict__ x) {
    size_t t = (size_t)blockIdx.x * 256 + threadIdx.x;
    size_t base = t * 8;
    float4 a = *reinterpret_cast<const float4*>(x + base);
    float4 b = *reinterpret_cast<const float4*>(x + base + 4);
    __align__(16) __half h[8];
    h[0] = __float2half_rn(a.x); h[1] = __float2half_rn(a.y);
    h[2] = __float2half_rn(a.z); h[3] = __float2half_rn(a.w);
    h[4] = __float2half_rn(b.x); h[5] = __float2half_rn(b.y);
    h[6] = __float2half_rn(b.z); h[7] = __float2half_rn(b.w);
    *reinterpret_cast<uint4*>(g_xh + base) = *reinterpret_cast<uint4*>(h);
}

// ---------------------------------------------------------------------------
// Kernel 2: fused dequant + fp16 GEMM, warp-specialized, split-K x4
//   grid = 1024 CTAs: bid -> (mt 0..3 fastest, kq 0..3, nt 0..63)
//   8 compute warps (tid<256) + 4 producer warps (dequant B into SMEM)
// ---------------------------------------------------------------------------
__global__ void __launch_bounds__(NTHREADS) gemm_fused_kernel(
    const int* __restrict__ wq, const float* __restrict__ ws) {
    extern __shared__ char smem[];
    uint32_t sb = smem_u32(smem);

    int tid = threadIdx.x;
    int lid = tid & 31;

    int bid = blockIdx.x;
    int mt = bid & 3;
    int kq = (bid >> 2) & 3;
    int nt = bid >> 4;
    int m0 = mt * TILE_M;
    int n0 = nt * TILE_N;
    int kbase = kq * K_UNIT;
    int wsrow = nt * (K_IN / 128) + kq * (K_UNIT / 128);  // scale row base

    const __half* xh = g_xh;

#define A_BASE(st) (sb + (uint32_t)(st) * STAGE_BYTES)
#define B_BASE(st) (sb + (uint32_t)(st) * STAGE_BYTES + A_STAGE_BYTES)

#define LOAD_A(st, chunk) do {                                                \
    int k0h = kbase + (chunk) * TILE_K;                                       \
    uint32_t ab = A_BASE(st);                                                 \
    _Pragma("unroll")                                                         \
    for (int i = 0; i < 4; ++i) {                                             \
        int seg = tid + i * 256;                                              \
        int row = seg >> 3, c = seg & 7;                                      \
        cp_async16(ab + sw128((uint32_t)row * 128 + c * 16),                  \
                   xh + (size_t)(m0 + row) * K_IN + k0h + c * 8);             \
    }                                                                         \
} while (0)

    if (tid < 256) {
        // ===================== COMPUTE WARPS =====================
        int wid = tid >> 5;
        int wm = wid >> 1, wn = wid & 1;          // 4x2 warp grid
        int m_warp = wm * 32, n_warp = wn * 64;   // warp tile 32m x 64n

        float acc[2][8][4];
#pragma unroll
        for (int mi = 0; mi < 2; ++mi)
#pragma unroll
            for (int ni = 0; ni < 8; ++ni)
#pragma unroll
                for (int j = 0; j < 4; ++j) acc[mi][ni][j] = 0.f;

        LOAD_A(0, 0);
        CP_COMMIT();
        LOAD_A(1, 1);
        CP_COMMIT();
        CP_WAIT1();                  // A(0) landed
        __syncthreads();             // B(0) also ready (producers)

        int cur = 0, nxt2 = 2;
#pragma unroll 1
        for (int it = 0; it < NCH; ++it) {
            if (it + 2 < NCH) LOAD_A(nxt2, it + 2);
            CP_COMMIT();

            uint32_t aBase = A_BASE(cur);
            uint32_t bBase = B_BASE(cur);
#pragma unroll
            for (int ks = 0; ks < 4; ++ks) {
                uint32_t af[2][4];
#pragma unroll
                for (int mi = 0; mi < 2; ++mi) {
                    uint32_t off = (uint32_t)(m_warp + mi * 16 + (lid & 15)) * 128
                                 + ks * 32 + ((lid >> 4) << 4);
                    ldmatrix_x4(af[mi], aBase + sw128(off));
                }
                uint32_t bf[8][2];
#pragma unroll
                for (int ntl = 0; ntl < 4; ++ntl) {
                    uint32_t r[4];
                    uint32_t off = (uint32_t)(n_warp + ntl * 16 + (lid & 7)
                                              + ((lid >> 4) << 3)) * 128
                                 + ks * 32 + (((lid >> 3) & 1) << 4);
                    ldmatrix_x4(r, bBase + sw128(off));
                    bf[2 * ntl][0] = r[0]; bf[2 * ntl][1] = r[1];
                    bf[2 * ntl + 1][0] = r[2]; bf[2 * ntl + 1][1] = r[3];
                }
#pragma unroll
                for (int mi = 0; mi < 2; ++mi)
#pragma unroll
                    for (int ni = 0; ni < 8; ++ni)
                        mma16816(acc[mi][ni], af[mi], bf[ni]);
            }

            CP_WAIT1();
            __syncthreads();

            cur = (cur == STAGES - 1) ? 0 : cur + 1;
            nxt2 = (nxt2 == STAGES - 1) ? 0 : nxt2 + 1;
        }

        // epilogue: fp16 partials to g_part[kq]
        __half* pout = g_part + (size_t)kq * ((size_t)M_ROWS * N_OUT);
#pragma unroll
        for (int mi = 0; mi < 2; ++mi) {
#pragma unroll
            for (int ni = 0; ni < 8; ++ni) {
                int row = m0 + m_warp + mi * 16 + (lid >> 2);
                int col = n0 + n_warp + ni * 8 + ((lid & 3) << 1);
                __half2 v0 = __floats2half2_rn(acc[mi][ni][0], acc[mi][ni][1]);
                __half2 v1 = __floats2half2_rn(acc[mi][ni][2], acc[mi][ni][3]);
                *reinterpret_cast<__half2*>(pout + (size_t)row * N_OUT + col) = v0;
                *reinterpret_cast<__half2*>(pout + (size_t)(row + 8) * N_OUT + col) = v1;
            }
        }
    } else {
        // ===================== PRODUCER WARPS (B dequant) =====================
        int ptid = tid - 256;                 // 0..127
        int seg = ptid & 15;                  // 16B segment within 256B chunk-row
        int rbase = ptid >> 4;                // 0..7

        // produce chunk `ch` into stage `st`
#define PRODUCE(st, ch) do {                                                  \
    int k0i = kbase + (ch) * TILE_K;                                          \
    float s = ws[wsrow + ((ch) >> 1)];                                        \
    uint32_t bb = B_BASE(st);                                                 \
    int4 q[16];                                                               \
    _Pragma("unroll")                                                         \
    for (int j = 0; j < 16; ++j) {                                            \
        int row = rbase + j * 8;                                              \
        q[j] = *reinterpret_cast<const int4*>(                                \
            wq + (size_t)(n0 + row) * K_IN + k0i + seg * 4);                  \
    }                                                                         \
    _Pragma("unroll")                                                         \
    for (int j = 0; j < 16; ++j) {                                            \
        int row = rbase + j * 8;                                              \
        __half2 pa = __floats2half2_rn(s * (float)q[j].x, s * (float)q[j].y); \
        __half2 pb = __floats2half2_rn(s * (float)q[j].z, s * (float)q[j].w); \
        sts64(bb + sw128((uint32_t)row * 128 + seg * 8),                      \
              *reinterpret_cast<uint32_t*>(&pa),                              \
              *reinterpret_cast<uint32_t*>(&pb));                             \
    }                                                                         \
} while (0)

        PRODUCE(0, 0);               // B(0) -> stage 0
        __syncthreads();

        int wst = 1;                 // stage for B(it+1)
#pragma unroll 1
        for (int it = 0; it < NCH; ++it) {
            if (it + 1 < NCH) PRODUCE(wst, it + 1);
            __syncthreads();
            wst = (wst == STAGES - 1) ? 0 : wst + 1;
        }
        // no epilogue work
#undef PRODUCE
    }
}

// ---------------------------------------------------------------------------
// Kernel 3: reduce 4 fp16 partials -> fp32 out
// ---------------------------------------------------------------------------
__global__ void __launch_bounds__(256) reduce_kernel(float* __restrict__ out) {
    size_t t = (size_t)blockIdx.x * 256 + threadIdx.x;
    size_t base = t * 8;
    const size_t SZ = (size_t)M_ROWS * N_OUT;
    float r[8];
#pragma unroll
    for (int j = 0; j < 8; ++j) r[j] = 0.f;
#pragma unroll
    for (int kq = 0; kq < KSPLIT; ++kq) {
        uint4 v = *reinterpret_cast<const uint4*>(g_part + kq * SZ + base);
        const __half2* h = reinterpret_cast<const __half2*>(&v);
#pragma unroll
        for (int j = 0; j < 4; ++j) {
            float2 f = __half22float2(h[j]);
            r[2 * j] += f.x;
            r[2 * j + 1] += f.y;
        }
    }
    float4 o0 = make_float4(r[0], r[1], r[2], r[3]);
    float4 o1 = make_float4(r[4], r[5], r[6], r[7]);
    *reinterpret_cast<float4*>(out + base) = o0;
    *reinterpret_cast<float4*>(out + base + 4) = o1;
}

// ---------------------------------------------------------------------------
// Launch
// ---------------------------------------------------------------------------
extern "C" void kernel_launch(void* const* d_in, const int* in_sizes, int n_in,
                              void* d_out, int out_size) {
    const float* x  = (const float*)d_in[0];
    const int*   wq = (const int*)d_in[1];     // int8 widened to int32 by harness
    const float* ws = (const float*)d_in[2];
    float* out = (float*)d_out;

    cvt_x_kernel<<<2048, 256>>>(x);

    cudaFuncSetAttribute(gemm_fused_kernel,
                         cudaFuncAttributeMaxDynamicSharedMemorySize, SMEM_TOTAL);
    // 1024 units: 4 mt x 4 kq x 64 nt (mt fastest for B sharing in L2)
    gemm_fused_kernel<<<1024, NTHREADS, SMEM_TOTAL>>>(wq, ws);

    // 512*8192 / 8 / 256 = 2048 blocks
    reduce_kernel<<<2048, 256>>>(out);
}